// round 4
// baseline (speedup 1.0000x reference)
#include <cuda_runtime.h>
#include <math.h>

#define NN 30000
#define EE 480000
#define EP 510000
#define LL 6
#define GG 128
#define FULL 0xffffffffu

typedef unsigned long long ull;

// ---------------- scratch (static device globals; no runtime alloc) ----------------
__device__ __align__(16) float d_h [NN*100];     // node features (updated in place)
__device__ __align__(16) float d_hx[NN*400];     // per-layer projected features
__device__ __align__(16) float d_es[LL*EE*4];    // edge attention bias per layer/head
__device__ __align__(16) float d_si[NN*4];
__device__ __align__(16) float d_sj[NN*4];
__device__ __align__(16) float d_weff[LL*400];   // a_j @ We  : [L][H][100]
__device__ int d_deg[NN];
__device__ int d_rowptr[NN+1];
__device__ int d_cursor[NN];
__device__ int d_csr_src[EP];
__device__ int d_csr_eid[EP];

// ---------------- f32x2 helpers (sm_103a packed fp32) ----------------
__device__ __forceinline__ ull fma2(ull a, ull b, ull c){
    ull r; asm("fma.rn.f32x2 %0, %1, %2, %3;" : "=l"(r) : "l"(a), "l"(b), "l"(c)); return r;
}
__device__ __forceinline__ ull pack2(float lo, float hi){
    ull r; asm("mov.b64 %0, {%1, %2};" : "=l"(r) : "f"(lo), "f"(hi)); return r;
}
__device__ __forceinline__ void unpack2(ull v, float &lo, float &hi){
    asm("mov.b64 {%0, %1}, %2;" : "=f"(lo), "=f"(hi) : "l"(v));
}

// ---------------- precompute kernels ----------------
__global__ void k_zero_deg(){
    int i = blockIdx.x*blockDim.x + threadIdx.x;
    if (i < NN) d_deg[i] = 0;
}

// w_eff[l][h][d] = sum_p a[l][h][100+p] * We[l][h*100+p][d]
__global__ void k_weff(const float* __restrict__ a, const float* __restrict__ We){
    int g = blockIdx.x*blockDim.x + threadIdx.x;
    if (g >= LL*400) return;
    int l = g/400, r = g%400, h = r/100, d = r%100;
    const float* ap = a  + l*800 + h*200 + 100;
    const float* wp = We + l*40000 + (h*100)*100 + d;
    float s = 0.f;
    #pragma unroll 4
    for (int p = 0; p < 100; p++) s = fmaf(ap[p], wp[p*100], s);
    d_weff[l*400 + h*100 + d] = s;
}

// es[l][e][h] = edge_attr[e] . w_eff[l][h]
__global__ void k_es(const float* __restrict__ ea){
    __shared__ float sw[LL*400];
    for (int i = threadIdx.x; i < LL*400; i += blockDim.x) sw[i] = d_weff[i];
    __syncthreads();
    int e = blockIdx.x*blockDim.x + threadIdx.x;
    if (e >= EE) return;
    const float4* row = (const float4*)(ea + (size_t)e*100);
    for (int l = 0; l < LL; l++){
        const float* wf = sw + l*400;
        float a0=0.f, a1=0.f, a2=0.f, a3=0.f;
        #pragma unroll 5
        for (int d4 = 0; d4 < 25; d4++){
            float4 v = row[d4];
            int b = d4*4;
            a0 += v.x*wf[b    ] + v.y*wf[b+1    ] + v.z*wf[b+2    ] + v.w*wf[b+3    ];
            a1 += v.x*wf[b+100] + v.y*wf[b+101] + v.z*wf[b+102] + v.w*wf[b+103];
            a2 += v.x*wf[b+200] + v.y*wf[b+201] + v.z*wf[b+202] + v.w*wf[b+203];
            a3 += v.x*wf[b+300] + v.y*wf[b+301] + v.z*wf[b+302] + v.w*wf[b+303];
        }
        *(float4*)(d_es + ((size_t)l*EE + e)*4) = make_float4(a0,a1,a2,a3);
    }
}

__global__ void k_h0(const int* __restrict__ x, const float* __restrict__ emb){
    int i = blockIdx.x*blockDim.x + threadIdx.x;
    if (i >= NN*25) return;
    int n = i/25, q = i%25;
    int atom = x[n];
    *(float4*)(d_h + n*100 + q*4) = *(const float4*)(emb + atom*100 + q*4);
}

// ---------------- CSR build (by dst, self-loops appended) ----------------
__global__ void k_hist(const int* __restrict__ ei){
    int e = blockIdx.x*blockDim.x + threadIdx.x;
    if (e >= EP) return;
    int dst = (e < EE) ? ei[EE + e] : (e - EE);
    atomicAdd(&d_deg[dst], 1);
}

__global__ void k_scan(){
    __shared__ int sh[1024];
    const int CH = 30;                 // 1024*30 >= 30000
    int t = threadIdx.x;
    int base = t*CH;
    int s = 0;
    for (int i = 0; i < CH; i++){ int idx = base+i; if (idx < NN) s += d_deg[idx]; }
    sh[t] = s; __syncthreads();
    for (int off = 1; off < 1024; off <<= 1){
        int v = (t >= off) ? sh[t-off] : 0;
        __syncthreads();
        sh[t] += v;
        __syncthreads();
    }
    int run = sh[t] - s;               // exclusive prefix for this chunk
    for (int i = 0; i < CH; i++){
        int idx = base+i;
        if (idx < NN){ d_rowptr[idx] = run; d_cursor[idx] = run; run += d_deg[idx]; }
    }
    if (t == 1023) d_rowptr[NN] = sh[1023];
}

__global__ void k_scatter(const int* __restrict__ ei){
    int e = blockIdx.x*blockDim.x + threadIdx.x;
    if (e >= EP) return;
    int dst, src, eid;
    if (e < EE){ dst = ei[EE+e]; src = ei[e]; eid = e; }
    else       { dst = e - EE;   src = dst;   eid = -1; }
    int pos = atomicAdd(&d_cursor[dst], 1);
    d_csr_src[pos] = src;
    d_csr_eid[pos] = eid;
}

// ---------------- per-layer GEMM: hx[n][j] = sum_d h[n][d]*W[j][d] ----------------
// block = 256 threads, 32 nodes; thread t owns columns j=t and j=t+256 (t<144);
// node pairs packed in f32x2 accumulators (2x fp32 throughput).
__global__ void __launch_bounds__(256,2) k_gemm(const float* __restrict__ Wl){
    __shared__ float hs[100][34];      // [d][node], pad 34 keeps LDS.64 aligned & low-conflict
    int tid = threadIdx.x;
    int node0 = blockIdx.x*32;
    for (int i = tid; i < 3200; i += 256){
        int nl = i/100, d = i%100;
        int n = node0 + nl;
        hs[d][nl] = (n < NN) ? d_h[n*100 + d] : 0.f;
    }
    __syncthreads();
    int j0 = tid;
    bool has1 = (tid + 256) < 400;
    const float* w0p = Wl + j0*100;
    const float* w1p = Wl + (has1 ? (j0+256) : j0)*100;
    ull acc0[16], acc1[16];
    #pragma unroll
    for (int k = 0; k < 16; k++){ acc0[k] = 0ull; acc1[k] = 0ull; }
    for (int d = 0; d < 100; d++){
        float a0 = __ldg(w0p + d);
        float a1 = has1 ? __ldg(w1p + d) : 0.f;
        ull w0 = pack2(a0, a0), w1 = pack2(a1, a1);
        const ull* hrow = (const ull*)(&hs[d][0]);   // broadcast LDS.64, conflict-free
        #pragma unroll
        for (int k = 0; k < 16; k++){
            ull hv = hrow[k];
            acc0[k] = fma2(hv, w0, acc0[k]);
            acc1[k] = fma2(hv, w1, acc1[k]);
        }
    }
    #pragma unroll
    for (int k = 0; k < 16; k++){
        int n0 = node0 + 2*k;
        float x0, x1; unpack2(acc0[k], x0, x1);
        if (n0   < NN) d_hx[n0*400 + j0] = x0;
        if (n0+1 < NN) d_hx[(n0+1)*400 + j0] = x1;
        if (has1){
            float y0, y1; unpack2(acc1[k], y0, y1);
            if (n0   < NN) d_hx[n0*400 + j0 + 256] = y0;
            if (n0+1 < NN) d_hx[(n0+1)*400 + j0 + 256] = y1;
        }
    }
}

// score_i / score_j per (node, head)
__global__ void k_score(const float* __restrict__ a, int l){
    int i = blockIdx.x*blockDim.x + threadIdx.x;
    if (i >= NN*4) return;
    int n = i >> 2, h = i & 3;
    const float* hp = d_hx + n*400 + h*100;
    const float* ai = a + l*800 + h*200;
    const float* aj = ai + 100;
    float si = 0.f, sj = 0.f;
    #pragma unroll 4
    for (int p = 0; p < 100; p++){
        float v = hp[p];
        si = fmaf(v, ai[p], si);
        sj = fmaf(v, aj[p], sj);
    }
    d_si[i] = si; d_sj[i] = sj;
}

// ---------------- node kernel: warp per node ----------------
// softmax over incoming edges + weighted aggregation of hx[src] + LayerNorm + ELU + residual
__global__ void __launch_bounds__(256) k_node(int l, const float* __restrict__ lng,
                                              const float* __restrict__ lnb){
    int lane = threadIdx.x & 31;
    int n = blockIdx.x*(blockDim.x >> 5) + (threadIdx.x >> 5);
    if (n >= NN) return;
    int rs = d_rowptr[n], re = d_rowptr[n+1];
    float4 si = *(const float4*)(d_si + n*4);

    // pass 1: per-head max of leaky_relu scores
    float m0=-1e30f, m1=-1e30f, m2=-1e30f, m3=-1e30f;
    for (int b = rs; b < re; b += 32){
        int idx = b + lane; bool ok = idx < re;
        int s   = ok ? d_csr_src[idx] : 0;
        int eid = ok ? d_csr_eid[idx] : -1;
        float4 sj = ok ? *(const float4*)(d_sj + s*4) : make_float4(0,0,0,0);
        float4 e4 = (eid >= 0) ? *(const float4*)(d_es + ((size_t)l*EE + eid)*4)
                               : make_float4(0,0,0,0);
        float v0 = si.x + sj.x + e4.x; v0 = v0 > 0.f ? v0 : 0.2f*v0; if(!ok) v0 = -1e30f;
        float v1 = si.y + sj.y + e4.y; v1 = v1 > 0.f ? v1 : 0.2f*v1; if(!ok) v1 = -1e30f;
        float v2 = si.z + sj.z + e4.z; v2 = v2 > 0.f ? v2 : 0.2f*v2; if(!ok) v2 = -1e30f;
        float v3 = si.w + sj.w + e4.w; v3 = v3 > 0.f ? v3 : 0.2f*v3; if(!ok) v3 = -1e30f;
        m0 = fmaxf(m0, v0); m1 = fmaxf(m1, v1); m2 = fmaxf(m2, v2); m3 = fmaxf(m3, v3);
    }
    #pragma unroll
    for (int off = 16; off; off >>= 1){
        m0 = fmaxf(m0, __shfl_xor_sync(FULL, m0, off));
        m1 = fmaxf(m1, __shfl_xor_sync(FULL, m1, off));
        m2 = fmaxf(m2, __shfl_xor_sync(FULL, m2, off));
        m3 = fmaxf(m3, __shfl_xor_sync(FULL, m3, off));
    }

    // pass 2: exp weights, denom, unnormalized per-head aggregation
    float den0=0.f, den1=0.f, den2=0.f, den3=0.f;
    float4 acc0 = make_float4(0,0,0,0), acc1 = acc0, acc2 = acc0, acc3 = acc0;
    const float4* hx4 = (const float4*)d_hx;
    for (int b = rs; b < re; b += 32){
        int idx = b + lane; bool ok = idx < re;
        int s   = ok ? d_csr_src[idx] : 0;
        int eid = ok ? d_csr_eid[idx] : -1;
        float4 sj = ok ? *(const float4*)(d_sj + s*4) : make_float4(0,0,0,0);
        float4 e4 = (eid >= 0) ? *(const float4*)(d_es + ((size_t)l*EE + eid)*4)
                               : make_float4(0,0,0,0);
        float v0 = si.x + sj.x + e4.x; v0 = v0 > 0.f ? v0 : 0.2f*v0;
        float v1 = si.y + sj.y + e4.y; v1 = v1 > 0.f ? v1 : 0.2f*v1;
        float v2 = si.z + sj.z + e4.z; v2 = v2 > 0.f ? v2 : 0.2f*v2;
        float v3 = si.w + sj.w + e4.w; v3 = v3 > 0.f ? v3 : 0.2f*v3;
        float e0 = ok ? __expf(v0 - m0) : 0.f;
        float e1 = ok ? __expf(v1 - m1) : 0.f;
        float e2 = ok ? __expf(v2 - m2) : 0.f;
        float e3 = ok ? __expf(v3 - m3) : 0.f;
        den0 += e0; den1 += e1; den2 += e2; den3 += e3;
        int cnt = min(32, re - b);
        for (int j = 0; j < cnt; j++){
            int   ss = __shfl_sync(FULL, s,  j);
            float w0 = __shfl_sync(FULL, e0, j);
            float w1 = __shfl_sync(FULL, e1, j);
            float w2 = __shfl_sync(FULL, e2, j);
            float w3 = __shfl_sync(FULL, e3, j);
            if (lane < 25){
                const float4* hp = hx4 + (size_t)ss*100;   // node base (400 floats)
                float4 x0 = hp[lane];
                float4 x1 = hp[25 + lane];
                float4 x2 = hp[50 + lane];
                float4 x3 = hp[75 + lane];
                acc0.x = fmaf(w0, x0.x, acc0.x); acc0.y = fmaf(w0, x0.y, acc0.y);
                acc0.z = fmaf(w0, x0.z, acc0.z); acc0.w = fmaf(w0, x0.w, acc0.w);
                acc1.x = fmaf(w1, x1.x, acc1.x); acc1.y = fmaf(w1, x1.y, acc1.y);
                acc1.z = fmaf(w1, x1.z, acc1.z); acc1.w = fmaf(w1, x1.w, acc1.w);
                acc2.x = fmaf(w2, x2.x, acc2.x); acc2.y = fmaf(w2, x2.y, acc2.y);
                acc2.z = fmaf(w2, x2.z, acc2.z); acc2.w = fmaf(w2, x2.w, acc2.w);
                acc3.x = fmaf(w3, x3.x, acc3.x); acc3.y = fmaf(w3, x3.y, acc3.y);
                acc3.z = fmaf(w3, x3.z, acc3.z); acc3.w = fmaf(w3, x3.w, acc3.w);
            }
        }
    }
    #pragma unroll
    for (int off = 16; off; off >>= 1){
        den0 += __shfl_xor_sync(FULL, den0, off);
        den1 += __shfl_xor_sync(FULL, den1, off);
        den2 += __shfl_xor_sync(FULL, den2, off);
        den3 += __shfl_xor_sync(FULL, den3, off);
    }
    float i0 = 1.f/(den0 + 1e-16f), i1 = 1.f/(den1 + 1e-16f);
    float i2 = 1.f/(den2 + 1e-16f), i3 = 1.f/(den3 + 1e-16f);
    float4 ag;
    ag.x = acc0.x*i0 + acc1.x*i1 + acc2.x*i2 + acc3.x*i3;
    ag.y = acc0.y*i0 + acc1.y*i1 + acc2.y*i2 + acc3.y*i3;
    ag.z = acc0.z*i0 + acc1.z*i1 + acc2.z*i2 + acc3.z*i3;
    ag.w = acc0.w*i0 + acc1.w*i1 + acc2.w*i2 + acc3.w*i3;

    // LayerNorm over 100 (lanes 0..24 hold 4 values each)
    float ls = (lane < 25) ? (ag.x + ag.y + ag.z + ag.w) : 0.f;
    #pragma unroll
    for (int off = 16; off; off >>= 1) ls += __shfl_xor_sync(FULL, ls, off);
    float mu = ls * 0.01f;
    float vs = 0.f;
    if (lane < 25){
        float dx = ag.x-mu, dy = ag.y-mu, dz = ag.z-mu, dw = ag.w-mu;
        vs = dx*dx + dy*dy + dz*dz + dw*dw;
    }
    #pragma unroll
    for (int off = 16; off; off >>= 1) vs += __shfl_xor_sync(FULL, vs, off);
    float rstd = rsqrtf(vs * 0.01f + 1e-5f);
    if (lane < 25){
        float4 g4   = *(const float4*)(lng + l*100 + lane*4);
        float4 b4   = *(const float4*)(lnb + l*100 + lane*4);
        float4 hold = *(const float4*)(d_h + n*100 + lane*4);
        float y;
        y = (ag.x-mu)*rstd*g4.x + b4.x; y = y > 0.f ? y : expm1f(y); hold.x += y;
        y = (ag.y-mu)*rstd*g4.y + b4.y; y = y > 0.f ? y : expm1f(y); hold.y += y;
        y = (ag.z-mu)*rstd*g4.z + b4.z; y = y > 0.f ? y : expm1f(y); hold.z += y;
        y = (ag.w-mu)*rstd*g4.w + b4.w; y = y > 0.f ? y : expm1f(y); hold.w += y;
        *(float4*)(d_h + n*100 + lane*4) = hold;
    }
}

// ---------------- pooling + MLP head (batch is sorted -> binary search bounds) ----------------
__global__ void k_pool(const int* __restrict__ batch,
                       const float* __restrict__ w1, const float* __restrict__ b1,
                       const float* __restrict__ w2, const float* __restrict__ b2,
                       float* __restrict__ out){
    __shared__ float pooled[100];
    __shared__ float hh[64];
    __shared__ int bounds[2];
    int g = blockIdx.x, t = threadIdx.x;
    if (t < 2){
        int v = g + t, lo = 0, hi = NN;
        while (lo < hi){ int m = (lo+hi) >> 1; if (batch[m] < v) lo = m+1; else hi = m; }
        bounds[t] = lo;
    }
    __syncthreads();
    int s0 = bounds[0], s1 = bounds[1];
    if (t < 100){
        float acc = 0.f;
        for (int n = s0; n < s1; n++) acc += d_h[n*100 + t];
        pooled[t] = acc / fmaxf((float)(s1 - s0), 1.f);
    }
    __syncthreads();
    if (t < 64){
        float s = b1[t];
        const float* wr = w1 + t*100;
        #pragma unroll 4
        for (int d = 0; d < 100; d++) s = fmaf(pooled[d], wr[d], s);
        hh[t] = s;
        out[128 + g*64 + t] = s;
    }
    __syncthreads();
    if (t == 0){
        float o = b2[0];
        for (int k = 0; k < 64; k++) o = fmaf(hh[k], w2[k], o);
        out[g] = o;
    }
}

// ---------------- launch ----------------
extern "C" void kernel_launch(void* const* d_in, const int* in_sizes, int n_in,
                              void* d_out, int out_size){
    (void)in_sizes; (void)n_in; (void)out_size;
    const int*   x     = (const int*)  d_in[0];
    const int*   ei    = (const int*)  d_in[1];
    const float* ea    = (const float*)d_in[2];
    const int*   batch = (const int*)  d_in[3];
    const float* emb   = (const float*)d_in[4];
    const float* W     = (const float*)d_in[5];
    const float* We    = (const float*)d_in[6];
    const float* a     = (const float*)d_in[7];
    const float* lng   = (const float*)d_in[8];
    const float* lnb   = (const float*)d_in[9];
    const float* w1    = (const float*)d_in[10];
    const float* b1    = (const float*)d_in[11];
    const float* w2    = (const float*)d_in[12];
    const float* b2    = (const float*)d_in[13];
    float* out = (float*)d_out;

    k_zero_deg<<<(NN+255)/256, 256>>>();
    k_weff<<<(LL*400+255)/256, 256>>>(a, We);
    k_es<<<(EE+255)/256, 256>>>(ea);
    k_h0<<<(NN*25+255)/256, 256>>>(x, emb);
    k_hist<<<(EP+255)/256, 256>>>(ei);
    k_scan<<<1, 1024>>>();
    k_scatter<<<(EP+255)/256, 256>>>(ei);
    for (int l = 0; l < LL; l++){
        k_gemm<<<(NN+31)/32, 256>>>(W + l*40000);
        k_score<<<(NN*4+255)/256, 256>>>(a, l);
        k_node<<<(NN+7)/8, 256>>>(l, lng, lnb);
    }
    k_pool<<<GG, 128>>>(batch, w1, b1, w2, b2, out);
}

// round 6
// speedup vs baseline: 1.0889x; 1.0889x over previous
#include <cuda_runtime.h>
#include <cuda_fp16.h>
#include <math.h>

#define NN 30000
#define EE 480000
#define EP 510000
#define LL 6
#define GG 128
#define FULL 0xffffffffu

typedef unsigned long long ull;

// ---------------- scratch (static device globals) ----------------
__device__ __align__(16) float  d_h  [NN*100];
__device__ __align__(16) float  d_hx [NN*400];      // fp32 hx (for scores)
__device__ __align__(16) __half d_hxh[NN*416];      // fp16 hx, heads padded to 104 (for gather)
__device__ __align__(16) float  d_es [LL*(size_t)EE*4];
__device__ __align__(16) float  d_si [NN*4];
__device__ __align__(16) float  d_sj [NN*4];
__device__ __align__(16) float  d_weff[LL*400];     // [l][d][h]
__device__ __align__(16) float  d_Wt [LL*40000];    // W transposed: [l][d][j]
__device__ int d_deg[NN];
__device__ int d_rowptr[NN+1];
__device__ int d_cursor[NN];
__device__ int d_csr_src[EP];
__device__ int d_csr_eid[EP];

// ---------------- f32x2 helpers ----------------
__device__ __forceinline__ ull fma2(ull a, ull b, ull c){
    ull r; asm("fma.rn.f32x2 %0, %1, %2, %3;" : "=l"(r) : "l"(a), "l"(b), "l"(c)); return r;
}
__device__ __forceinline__ ull pack2(float lo, float hi){
    ull r; asm("mov.b64 %0, {%1, %2};" : "=l"(r) : "f"(lo), "f"(hi)); return r;
}
__device__ __forceinline__ void unpack2(ull v, float &lo, float &hi){
    asm("mov.b64 {%0, %1}, %2;" : "=f"(lo), "=f"(hi) : "l"(v));
}

// ---------------- precompute ----------------
__global__ void k_zero_deg(){
    int i = blockIdx.x*blockDim.x + threadIdx.x;
    if (i < NN) d_deg[i] = 0;
}

// pad columns of fp16 hx are never written by gemm; zero them once
__global__ void k_zpad(){
    int i = blockIdx.x*blockDim.x + threadIdx.x;
    if (i >= NN*16) return;
    int n = i/16, k = i%16, h = k/4, p = k%4;
    d_hxh[(size_t)n*416 + h*104 + 100 + p] = __float2half(0.f);
}

// w_eff[l][d][h] = sum_p a[l][h][100+p] * We[l][h*100+p][d]
__global__ void k_weff(const float* __restrict__ a, const float* __restrict__ We){
    int g = blockIdx.x*blockDim.x + threadIdx.x;
    if (g >= LL*400) return;
    int l = g/400, r = g%400, h = r/100, d = r%100;
    const float* ap = a  + l*800 + h*200 + 100;
    const float* wp = We + l*40000 + (h*100)*100 + d;
    float s = 0.f;
    #pragma unroll 4
    for (int p = 0; p < 100; p++) s = fmaf(ap[p], wp[p*100], s);
    d_weff[l*400 + d*4 + h] = s;
}

// Wt[l][d][j] = W[l][j][d]
__global__ void k_wt(const float* __restrict__ W){
    int i = blockIdx.x*blockDim.x + threadIdx.x;
    if (i >= LL*40000) return;
    int l = i/40000, r = i%40000, d = r/400, j = r%400;
    d_Wt[i] = W[l*40000 + j*100 + d];
}

// es[l][e][h] = edge_attr[e] . w_eff[l][h]  (smem-staged edge rows, coalesced)
__global__ void __launch_bounds__(64) k_es(const float* __restrict__ ea){
    __shared__ __align__(16) float sw[LL*400];
    __shared__ float rows[64*101];
    int tid = threadIdx.x;
    for (int i = tid; i < LL*400; i += 64) sw[i] = d_weff[i];
    int e0 = blockIdx.x*64;
    for (int i = tid; i < 64*100; i += 64){
        int el = i/100, d = i%100;
        int e = e0 + el;
        rows[el*101 + d] = (e < EE) ? ea[(size_t)e*100 + d] : 0.f;
    }
    __syncthreads();
    int e = e0 + tid;
    if (e >= EE) return;
    const float* rp = rows + tid*101;
    for (int l = 0; l < LL; l++){
        const float4* wl = (const float4*)(sw + l*400);
        float a0=0.f, a1=0.f, a2=0.f, a3=0.f;
        #pragma unroll 4
        for (int d = 0; d < 100; d++){
            float v = rp[d];
            float4 wv = wl[d];
            a0 = fmaf(v, wv.x, a0);
            a1 = fmaf(v, wv.y, a1);
            a2 = fmaf(v, wv.z, a2);
            a3 = fmaf(v, wv.w, a3);
        }
        *(float4*)(d_es + ((size_t)l*EE + e)*4) = make_float4(a0,a1,a2,a3);
    }
}

__global__ void k_h0(const int* __restrict__ x, const float* __restrict__ emb){
    int i = blockIdx.x*blockDim.x + threadIdx.x;
    if (i >= NN*25) return;
    int n = i/25, q = i%25;
    int atom = x[n];
    *(float4*)(d_h + n*100 + q*4) = *(const float4*)(emb + atom*100 + q*4);
}

// ---------------- CSR build ----------------
__global__ void k_hist(const int* __restrict__ ei){
    int e = blockIdx.x*blockDim.x + threadIdx.x;
    if (e >= EP) return;
    int dst = (e < EE) ? ei[EE + e] : (e - EE);
    atomicAdd(&d_deg[dst], 1);
}

__global__ void k_scan(){
    __shared__ int sh[1024];
    const int CH = 30;
    int t = threadIdx.x;
    int base = t*CH;
    int s = 0;
    for (int i = 0; i < CH; i++){ int idx = base+i; if (idx < NN) s += d_deg[idx]; }
    sh[t] = s; __syncthreads();
    for (int off = 1; off < 1024; off <<= 1){
        int v = (t >= off) ? sh[t-off] : 0;
        __syncthreads();
        sh[t] += v;
        __syncthreads();
    }
    int run = sh[t] - s;
    for (int i = 0; i < CH; i++){
        int idx = base+i;
        if (idx < NN){ d_rowptr[idx] = run; d_cursor[idx] = run; run += d_deg[idx]; }
    }
    if (t == 1023) d_rowptr[NN] = sh[1023];
}

__global__ void k_scatter(const int* __restrict__ ei){
    int e = blockIdx.x*blockDim.x + threadIdx.x;
    if (e >= EP) return;
    int dst, src, eid;
    if (e < EE){ dst = ei[EE+e]; src = ei[e]; eid = e; }
    else       { dst = e - EE;   src = dst;   eid = -1; }
    int pos = atomicAdd(&d_cursor[dst], 1);
    d_csr_src[pos] = src;
    d_csr_eid[pos] = eid;
}

// ---------------- per-layer GEMM (coalesced transposed weights) ----------------
__global__ void __launch_bounds__(256,2) k_gemm(int l){
    __shared__ float hs[100][34];
    int tid = threadIdx.x;
    int node0 = blockIdx.x*32;
    const float* Wtl = d_Wt + l*40000;
    for (int i = tid; i < 3200; i += 256){
        int nl = i/100, d = i%100;
        int n = node0 + nl;
        hs[d][nl] = (n < NN) ? d_h[n*100 + d] : 0.f;
    }
    __syncthreads();
    int j0 = tid;
    bool has1 = (tid + 256) < 400;
    ull acc0[16], acc1[16];
    #pragma unroll
    for (int k = 0; k < 16; k++){ acc0[k] = 0ull; acc1[k] = 0ull; }
    for (int d = 0; d < 100; d++){
        float a0 = __ldg(Wtl + d*400 + j0);                 // coalesced
        float a1 = has1 ? __ldg(Wtl + d*400 + j0 + 256) : 0.f;
        ull w0 = pack2(a0, a0), w1 = pack2(a1, a1);
        const ull* hrow = (const ull*)(&hs[d][0]);
        #pragma unroll
        for (int k = 0; k < 16; k++){
            ull hv = hrow[k];
            acc0[k] = fma2(hv, w0, acc0[k]);
            acc1[k] = fma2(hv, w1, acc1[k]);
        }
    }
    int mj0 = (j0/100)*104 + j0%100;
    int mj1 = ((j0+256)/100)*104 + (j0+256)%100;
    #pragma unroll
    for (int k = 0; k < 16; k++){
        int n0 = node0 + 2*k;
        float x0, x1; unpack2(acc0[k], x0, x1);
        if (n0 < NN){
            d_hx[(size_t)n0*400 + j0] = x0;
            d_hxh[(size_t)n0*416 + mj0] = __float2half_rn(x0);
        }
        if (n0+1 < NN){
            d_hx[(size_t)(n0+1)*400 + j0] = x1;
            d_hxh[(size_t)(n0+1)*416 + mj0] = __float2half_rn(x1);
        }
        if (has1){
            float y0, y1; unpack2(acc1[k], y0, y1);
            if (n0 < NN){
                d_hx[(size_t)n0*400 + j0 + 256] = y0;
                d_hxh[(size_t)n0*416 + mj1] = __float2half_rn(y0);
            }
            if (n0+1 < NN){
                d_hx[(size_t)(n0+1)*400 + j0 + 256] = y1;
                d_hxh[(size_t)(n0+1)*416 + mj1] = __float2half_rn(y1);
            }
        }
    }
}

// ---------------- scores: warp per node, coalesced ----------------
__global__ void __launch_bounds__(256) k_score(const float* __restrict__ a, int l){
    __shared__ __align__(16) float sa[800];
    int tid = threadIdx.x;
    for (int i = tid; i < 800; i += 256) sa[i] = a[l*800 + i];
    __syncthreads();
    int lane = tid & 31, w = tid >> 5;
    int n = blockIdx.x*8 + w;
    if (n >= NN) return;
    const float4* hp = (const float4*)(d_hx + (size_t)n*400);
    float s0=0,s1=0,s2=0,s3=0, t0=0,t1=0,t2=0,t3=0;
    #pragma unroll
    for (int c = 0; c < 4; c++){
        int q = lane + c*32;
        if (q >= 100) break;
        float4 x = hp[q];
        int h = q/25, p4 = q%25;
        const float4* ab = (const float4*)(sa + h*200);
        float4 A = ab[p4], J = ab[25 + p4];
        float di = x.x*A.x + x.y*A.y + x.z*A.z + x.w*A.w;
        float dj = x.x*J.x + x.y*J.y + x.z*J.z + x.w*J.w;
        if      (h == 0){ s0 += di; t0 += dj; }
        else if (h == 1){ s1 += di; t1 += dj; }
        else if (h == 2){ s2 += di; t2 += dj; }
        else            { s3 += di; t3 += dj; }
    }
    #pragma unroll
    for (int off = 16; off; off >>= 1){
        s0 += __shfl_xor_sync(FULL, s0, off); s1 += __shfl_xor_sync(FULL, s1, off);
        s2 += __shfl_xor_sync(FULL, s2, off); s3 += __shfl_xor_sync(FULL, s3, off);
        t0 += __shfl_xor_sync(FULL, t0, off); t1 += __shfl_xor_sync(FULL, t1, off);
        t2 += __shfl_xor_sync(FULL, t2, off); t3 += __shfl_xor_sync(FULL, t3, off);
    }
    if (lane < 4){
        float vi = lane==0?s0 : lane==1?s1 : lane==2?s2 : s3;
        float vj = lane==0?t0 : lane==1?t1 : lane==2?t2 : t3;
        d_si[n*4 + lane] = vi;
        d_sj[n*4 + lane] = vj;
    }
}

// ---------------- node kernel: warp per node, fp16 gather ----------------
__global__ void __launch_bounds__(256) k_node(int l, const float* __restrict__ lng,
                                              const float* __restrict__ lnb){
    __shared__ float stage[8][416];
    int lane = threadIdx.x & 31, w = threadIdx.x >> 5;
    int n = blockIdx.x*8 + w;
    if (n >= NN) return;
    int rs = d_rowptr[n], re = d_rowptr[n+1];
    float4 si = *(const float4*)(d_si + n*4);
    int h0 = lane/13;                 // 0..2
    int h1 = (lane+32)/13;            // 2..3
    bool hasQ1 = lane < 20;

    // pass 1: per-head max of leaky_relu scores
    float m0=-1e30f, m1=-1e30f, m2=-1e30f, m3=-1e30f;
    for (int b = rs; b < re; b += 32){
        int idx = b + lane; bool ok = idx < re;
        int s   = ok ? d_csr_src[idx] : 0;
        int eid = ok ? d_csr_eid[idx] : -1;
        float4 sj = ok ? *(const float4*)(d_sj + s*4) : make_float4(0,0,0,0);
        float4 e4 = (eid >= 0) ? *(const float4*)(d_es + ((size_t)l*EE + eid)*4)
                               : make_float4(0,0,0,0);
        float v0 = si.x + sj.x + e4.x; v0 = v0 > 0.f ? v0 : 0.2f*v0; if(!ok) v0 = -1e30f;
        float v1 = si.y + sj.y + e4.y; v1 = v1 > 0.f ? v1 : 0.2f*v1; if(!ok) v1 = -1e30f;
        float v2 = si.z + sj.z + e4.z; v2 = v2 > 0.f ? v2 : 0.2f*v2; if(!ok) v2 = -1e30f;
        float v3 = si.w + sj.w + e4.w; v3 = v3 > 0.f ? v3 : 0.2f*v3; if(!ok) v3 = -1e30f;
        m0 = fmaxf(m0, v0); m1 = fmaxf(m1, v1); m2 = fmaxf(m2, v2); m3 = fmaxf(m3, v3);
    }
    #pragma unroll
    for (int off = 16; off; off >>= 1){
        m0 = fmaxf(m0, __shfl_xor_sync(FULL, m0, off));
        m1 = fmaxf(m1, __shfl_xor_sync(FULL, m1, off));
        m2 = fmaxf(m2, __shfl_xor_sync(FULL, m2, off));
        m3 = fmaxf(m3, __shfl_xor_sync(FULL, m3, off));
    }

    // pass 2: softmax weights + fp16 gather
    float den0=0.f, den1=0.f, den2=0.f, den3=0.f;
    float acc0[8], acc1[8];
    #pragma unroll
    for (int k = 0; k < 8; k++){ acc0[k] = 0.f; acc1[k] = 0.f; }
    for (int b = rs; b < re; b += 32){
        int idx = b + lane; bool ok = idx < re;
        int s   = ok ? d_csr_src[idx] : 0;
        int eid = ok ? d_csr_eid[idx] : -1;
        float4 sj = ok ? *(const float4*)(d_sj + s*4) : make_float4(0,0,0,0);
        float4 e4 = (eid >= 0) ? *(const float4*)(d_es + ((size_t)l*EE + eid)*4)
                               : make_float4(0,0,0,0);
        float v0 = si.x + sj.x + e4.x; v0 = v0 > 0.f ? v0 : 0.2f*v0;
        float v1 = si.y + sj.y + e4.y; v1 = v1 > 0.f ? v1 : 0.2f*v1;
        float v2 = si.z + sj.z + e4.z; v2 = v2 > 0.f ? v2 : 0.2f*v2;
        float v3 = si.w + sj.w + e4.w; v3 = v3 > 0.f ? v3 : 0.2f*v3;
        float e0 = ok ? __expf(v0 - m0) : 0.f;
        float e1 = ok ? __expf(v1 - m1) : 0.f;
        float e2 = ok ? __expf(v2 - m2) : 0.f;
        float e3 = ok ? __expf(v3 - m3) : 0.f;
        den0 += e0; den1 += e1; den2 += e2; den3 += e3;
        int cnt = min(32, re - b);
        for (int j = 0; j < cnt; j++){
            int   ss = __shfl_sync(FULL, s,  j);
            float w0 = __shfl_sync(FULL, e0, j);
            float w1 = __shfl_sync(FULL, e1, j);
            float w2 = __shfl_sync(FULL, e2, j);
            float w3 = __shfl_sync(FULL, e3, j);
            float w0s = (h0==0) ? w0 : (h0==1) ? w1 : w2;
            float w1s = (h1==2) ? w2 : w3;
            const uint4* bp = (const uint4*)(d_hxh + (size_t)ss*416);
            uint4 A = __ldg(bp + lane);
            float2 f;
            f = __half22float2(*(__half2*)&A.x); acc0[0] = fmaf(w0s, f.x, acc0[0]); acc0[1] = fmaf(w0s, f.y, acc0[1]);
            f = __half22float2(*(__half2*)&A.y); acc0[2] = fmaf(w0s, f.x, acc0[2]); acc0[3] = fmaf(w0s, f.y, acc0[3]);
            f = __half22float2(*(__half2*)&A.z); acc0[4] = fmaf(w0s, f.x, acc0[4]); acc0[5] = fmaf(w0s, f.y, acc0[5]);
            f = __half22float2(*(__half2*)&A.w); acc0[6] = fmaf(w0s, f.x, acc0[6]); acc0[7] = fmaf(w0s, f.y, acc0[7]);
            if (hasQ1){
                uint4 B = __ldg(bp + 32 + lane);
                f = __half22float2(*(__half2*)&B.x); acc1[0] = fmaf(w1s, f.x, acc1[0]); acc1[1] = fmaf(w1s, f.y, acc1[1]);
                f = __half22float2(*(__half2*)&B.y); acc1[2] = fmaf(w1s, f.x, acc1[2]); acc1[3] = fmaf(w1s, f.y, acc1[3]);
                f = __half22float2(*(__half2*)&B.z); acc1[4] = fmaf(w1s, f.x, acc1[4]); acc1[5] = fmaf(w1s, f.y, acc1[5]);
                f = __half22float2(*(__half2*)&B.w); acc1[6] = fmaf(w1s, f.x, acc1[6]); acc1[7] = fmaf(w1s, f.y, acc1[7]);
            }
        }
    }
    #pragma unroll
    for (int off = 16; off; off >>= 1){
        den0 += __shfl_xor_sync(FULL, den0, off);
        den1 += __shfl_xor_sync(FULL, den1, off);
        den2 += __shfl_xor_sync(FULL, den2, off);
        den3 += __shfl_xor_sync(FULL, den3, off);
    }
    float i0 = 1.f/(den0 + 1e-16f), i1 = 1.f/(den1 + 1e-16f);
    float i2 = 1.f/(den2 + 1e-16f), i3 = 1.f/(den3 + 1e-16f);
    float sc0 = (h0==0) ? i0 : (h0==1) ? i1 : i2;
    float sc1 = (h1==2) ? i2 : i3;

    float* sp = &stage[w][0];
    *(float4*)(sp + lane*8)     = make_float4(acc0[0]*sc0, acc0[1]*sc0, acc0[2]*sc0, acc0[3]*sc0);
    *(float4*)(sp + lane*8 + 4) = make_float4(acc0[4]*sc0, acc0[5]*sc0, acc0[6]*sc0, acc0[7]*sc0);
    if (hasQ1){
        *(float4*)(sp + (32+lane)*8)     = make_float4(acc1[0]*sc1, acc1[1]*sc1, acc1[2]*sc1, acc1[3]*sc1);
        *(float4*)(sp + (32+lane)*8 + 4) = make_float4(acc1[4]*sc1, acc1[5]*sc1, acc1[6]*sc1, acc1[7]*sc1);
    }
    __syncwarp();

    float4 ag = make_float4(0,0,0,0);
    if (lane < 25){
        #pragma unroll
        for (int h = 0; h < 4; h++){
            float4 v = *(const float4*)(sp + h*104 + lane*4);
            ag.x += v.x; ag.y += v.y; ag.z += v.z; ag.w += v.w;
        }
    }

    // LayerNorm over 100 dims
    float ls = (lane < 25) ? (ag.x + ag.y + ag.z + ag.w) : 0.f;
    #pragma unroll
    for (int off = 16; off; off >>= 1) ls += __shfl_xor_sync(FULL, ls, off);
    float mu = ls * 0.01f;
    float vs = 0.f;
    if (lane < 25){
        float dx = ag.x-mu, dy = ag.y-mu, dz = ag.z-mu, dw = ag.w-mu;
        vs = dx*dx + dy*dy + dz*dz + dw*dw;
    }
    #pragma unroll
    for (int off = 16; off; off >>= 1) vs += __shfl_xor_sync(FULL, vs, off);
    float rstd = rsqrtf(vs * 0.01f + 1e-5f);
    if (lane < 25){
        float4 g4   = *(const float4*)(lng + l*100 + lane*4);
        float4 b4   = *(const float4*)(lnb + l*100 + lane*4);
        float4 hold = *(const float4*)(d_h + n*100 + lane*4);
        float y;
        y = (ag.x-mu)*rstd*g4.x + b4.x; y = y > 0.f ? y : expm1f(y); hold.x += y;
        y = (ag.y-mu)*rstd*g4.y + b4.y; y = y > 0.f ? y : expm1f(y); hold.y += y;
        y = (ag.z-mu)*rstd*g4.z + b4.z; y = y > 0.f ? y : expm1f(y); hold.z += y;
        y = (ag.w-mu)*rstd*g4.w + b4.w; y = y > 0.f ? y : expm1f(y); hold.w += y;
        *(float4*)(d_h + n*100 + lane*4) = hold;
    }
}

// ---------------- pooling + MLP head ----------------
__global__ void k_pool(const int* __restrict__ batch,
                       const float* __restrict__ w1, const float* __restrict__ b1,
                       const float* __restrict__ w2, const float* __restrict__ b2,
                       float* __restrict__ out){
    __shared__ float pooled[100];
    __shared__ float hh[64];
    __shared__ int bounds[2];
    int g = blockIdx.x, t = threadIdx.x;
    if (t < 2){
        int v = g + t, lo = 0, hi = NN;
        while (lo < hi){ int m = (lo+hi) >> 1; if (batch[m] < v) lo = m+1; else hi = m; }
        bounds[t] = lo;
    }
    __syncthreads();
    int s0 = bounds[0], s1 = bounds[1];
    if (t < 100){
        float acc = 0.f;
        for (int n = s0; n < s1; n++) acc += d_h[n*100 + t];
        pooled[t] = acc / fmaxf((float)(s1 - s0), 1.f);
    }
    __syncthreads();
    if (t < 64){
        float s = b1[t];
        const float* wr = w1 + t*100;
        #pragma unroll 4
        for (int d = 0; d < 100; d++) s = fmaf(pooled[d], wr[d], s);
        hh[t] = s;
        out[128 + g*64 + t] = s;
    }
    __syncthreads();
    if (t == 0){
        float o = b2[0];
        for (int k = 0; k < 64; k++) o = fmaf(hh[k], w2[k], o);
        out[g] = o;
    }
}

// ---------------- launch ----------------
extern "C" void kernel_launch(void* const* d_in, const int* in_sizes, int n_in,
                              void* d_out, int out_size){
    (void)in_sizes; (void)n_in; (void)out_size;
    const int*   x     = (const int*)  d_in[0];
    const int*   ei    = (const int*)  d_in[1];
    const float* ea    = (const float*)d_in[2];
    const int*   batch = (const int*)  d_in[3];
    const float* emb   = (const float*)d_in[4];
    const float* W     = (const float*)d_in[5];
    const float* We    = (const float*)d_in[6];
    const float* a     = (const float*)d_in[7];
    const float* lng   = (const float*)d_in[8];
    const float* lnb   = (const float*)d_in[9];
    const float* w1    = (const float*)d_in[10];
    const float* b1    = (const float*)d_in[11];
    const float* w2    = (const float*)d_in[12];
    const float* b2    = (const float*)d_in[13];
    float* out = (float*)d_out;

    k_zero_deg<<<(NN+255)/256, 256>>>();
    k_zpad<<<(NN*16+255)/256, 256>>>();
    k_weff<<<(LL*400+255)/256, 256>>>(a, We);
    k_wt<<<(LL*40000+255)/256, 256>>>(W);
    k_es<<<(EE+63)/64, 64>>>(ea);
    k_h0<<<(NN*25+255)/256, 256>>>(x, emb);
    k_hist<<<(EP+255)/256, 256>>>(ei);
    k_scan<<<1, 1024>>>();
    k_scatter<<<(EP+255)/256, 256>>>(ei);
    for (int l = 0; l < LL; l++){
        k_gemm<<<(NN+31)/32, 256>>>(l);
        k_score<<<(NN+7)/8, 256>>>(a, l);
        k_node<<<(NN+7)/8, 256>>>(l, lng, lnb);
    }
    k_pool<<<GG, 128>>>(batch, w1, b1, w2, b2, out);
}